// round 2
// baseline (speedup 1.0000x reference)
#include <cuda_runtime.h>
#include <cstdint>

#define N_NODES 50000
#define N_EDGES 600000
#define HID     128
#define N_GRAPHS 32
#define D_OUT   3

typedef unsigned long long u64;

// ---------------- scratch (device globals; no allocs) ----------------
__device__ int   g_cnt[N_NODES];
__device__ int   g_rowptr[N_NODES + 1];
__device__ int   g_cursor[N_NODES];
__device__ int   g_col[N_EDGES];
__device__ float g_aggr[(size_t)N_NODES * HID];
__device__ float g_bufA[(size_t)N_NODES * HID];
__device__ float g_bufB[(size_t)N_NODES * HID];
__device__ float g_gsum[N_GRAPHS * HID];
__device__ float g_gcnt[N_GRAPHS];

// ---------------- small helpers ----------------
__device__ __forceinline__ u64 pack_dup(float a) {
    u64 r;
    asm("mov.b64 %0, {%1,%1};" : "=l"(r) : "f"(a));
    return r;
}
__device__ __forceinline__ float2 unpack2(u64 v) {
    float2 r;
    asm("mov.b64 {%0,%1}, %2;" : "=f"(r.x), "=f"(r.y) : "l"(v));
    return r;
}
__device__ __forceinline__ void ffma2(u64& acc, u64 a, u64 b) {
    asm("fma.rn.f32x2 %0, %1, %2, %0;" : "+l"(acc) : "l"(a), "l"(b));
}

// ---------------- CSR build ----------------
__global__ void zero_kernel() {
    int i = blockIdx.x * blockDim.x + threadIdx.x;
    if (i < N_NODES) g_cnt[i] = 0;
    if (i < N_GRAPHS * HID) g_gsum[i] = 0.0f;
    if (i < N_GRAPHS) g_gcnt[i] = 0.0f;
}

__global__ void hist_kernel(const int* __restrict__ dst) {
    int e = blockIdx.x * blockDim.x + threadIdx.x;
    if (e < N_EDGES) atomicAdd(&g_cnt[dst[e]], 1);
}

// single-block exclusive scan over g_cnt -> g_rowptr / g_cursor
__global__ void scan_kernel() {
    __shared__ int warp_sums[32];
    __shared__ int s_carry;
    int tid = threadIdx.x, lane = tid & 31, wid = tid >> 5;
    if (tid == 0) { s_carry = 0; g_rowptr[0] = 0; }
    __syncthreads();
    for (int base = 0; base < N_NODES; base += 1024) {
        int i = base + tid;
        int v = (i < N_NODES) ? g_cnt[i] : 0;
        int x = v;
        #pragma unroll
        for (int off = 1; off < 32; off <<= 1) {
            int t = __shfl_up_sync(0xffffffffu, x, off);
            if (lane >= off) x += t;
        }
        if (lane == 31) warp_sums[wid] = x;
        __syncthreads();
        if (wid == 0) {
            int w = warp_sums[lane];
            #pragma unroll
            for (int off = 1; off < 32; off <<= 1) {
                int t = __shfl_up_sync(0xffffffffu, w, off);
                if (lane >= off) w += t;
            }
            warp_sums[lane] = w;
        }
        __syncthreads();
        int incl = x + (wid > 0 ? warp_sums[wid - 1] : 0) + s_carry;
        if (i < N_NODES) {
            g_rowptr[i + 1] = incl;
            g_cursor[i] = incl - v;
        }
        __syncthreads();
        if (tid == 1023) s_carry = incl;
        __syncthreads();
    }
}

__global__ void fill_kernel(const int* __restrict__ src,
                            const int* __restrict__ dst) {
    int e = blockIdx.x * blockDim.x + threadIdx.x;
    if (e < N_EDGES) {
        int d = dst[e];
        int p = atomicAdd(&g_cursor[d], 1);
        g_col[p] = src[e];
    }
}

// ---------------- aggregation: warp per node, float4 per lane ----------------
__global__ void agg_kernel(const float* __restrict__ in, float* __restrict__ out) {
    int node = (blockIdx.x * blockDim.x + threadIdx.x) >> 5;
    int lane = threadIdx.x & 31;
    if (node >= N_NODES) return;
    int s = g_rowptr[node];
    int e = g_rowptr[node + 1];
    float4 acc = make_float4(0.f, 0.f, 0.f, 0.f);
    for (int j = s; j < e; j++) {
        int sn = g_col[j];
        float4 v = *(const float4*)(in + (size_t)sn * HID + lane * 4);
        acc.x += v.x; acc.y += v.y; acc.z += v.z; acc.w += v.w;
    }
    int deg = e - s;
    float inv = 1.0f / (float)(deg > 0 ? deg : 1);
    acc.x *= inv; acc.y *= inv; acc.z *= inv; acc.w *= inv;
    *(float4*)(out + (size_t)node * HID + lane * 4) = acc;
}

// ---------------- fused GEMM: out = act(A@WA^T [+ B@WB^T] + bias) ----------------
// 128x128 block tile, 256 threads, 8x8 microtile, packed fma.rn.f32x2.
__global__ void __launch_bounds__(256, 1)
gemm_kernel(const float* __restrict__ A, const float* __restrict__ WA,
            const float* __restrict__ B, const float* __restrict__ WB,
            const float* __restrict__ bias, float* __restrict__ out,
            int M, int do_relu, int dual) {
    extern __shared__ float smem[];
    float* sIn = smem;           // [row*128 + k], row-major
    float* sW  = smem + 16384;   // k-major, float4 XOR-swizzled along cols

    int tid = threadIdx.x;
    int tx = tid & 15;       // col group (8 cols)
    int ty = tid >> 4;       // row group (8 rows)
    int m0 = blockIdx.x * 128;
    int lane = tid & 31;
    int sub  = tid >> 5;     // 0..7

    u64 acc[8][4];
    #pragma unroll
    for (int r = 0; r < 8; r++)
        #pragma unroll
        for (int c = 0; c < 4; c++) acc[r][c] = 0ull;

    int npass = dual ? 2 : 1;
    for (int pass = 0; pass < npass; pass++) {
        const float* inp = pass ? B : A;
        const float* w   = pass ? WB : WA;
        if (pass) __syncthreads();   // protect smem reads of previous pass

        // load input tile [128 rows x 128 k], rows guarded
        #pragma unroll
        for (int it = 0; it < 16; it++) {
            int row = it * 8 + sub;
            int grow = m0 + row;
            float4 v = make_float4(0.f, 0.f, 0.f, 0.f);
            if (grow < M) v = *(const float4*)(inp + (size_t)grow * 128 + lane * 4);
            *(float4*)(sIn + row * 128 + lane * 4) = v;
        }
        // load W transposed into k-major with float4 XOR swizzle:
        // logical (k, c4) lives at sW[k*128 + ((c4 ^ ((k>>2)&31))<<2)]
        #pragma unroll
        for (int it = 0; it < 16; it++) {
            int col = it * 8 + sub;
            float4 v = *(const float4*)(w + col * 128 + (lane << 2));
            int c4 = col >> 2;
            int cl = col & 3;
            float vv[4] = {v.x, v.y, v.z, v.w};
            #pragma unroll
            for (int i = 0; i < 4; i++) {
                int k = (lane << 2) + i;     // (k>>2)&31 == lane
                sW[k * 128 + (((c4 ^ lane)) << 2) + cl] = vv[i];
            }
        }
        __syncthreads();

        #pragma unroll 4
        for (int k = 0; k < 128; k++) {
            u64 a2[8];
            #pragma unroll
            for (int r = 0; r < 8; r++)
                a2[r] = pack_dup(sIn[(ty * 8 + r) * 128 + k]);
            int swz = (k >> 2) & 31;
            const float* wr = sW + k * 128;
            ulonglong2 bb0 = *(const ulonglong2*)(wr + ((((tx << 1)    ) ^ swz) << 2));
            ulonglong2 bb1 = *(const ulonglong2*)(wr + ((((tx << 1) | 1) ^ swz) << 2));
            u64 b[4] = {bb0.x, bb0.y, bb1.x, bb1.y};
            #pragma unroll
            for (int r = 0; r < 8; r++)
                #pragma unroll
                for (int c = 0; c < 4; c++)
                    ffma2(acc[r][c], a2[r], b[c]);
        }
    }

    // epilogue
    float bv[8];
    #pragma unroll
    for (int j = 0; j < 8; j++) bv[j] = bias[tx * 8 + j];

    #pragma unroll
    for (int r = 0; r < 8; r++) {
        int grow = m0 + ty * 8 + r;
        if (grow < M) {
            float o[8];
            #pragma unroll
            for (int c = 0; c < 4; c++) {
                float2 v = unpack2(acc[r][c]);
                o[2 * c]     = v.x + bv[2 * c];
                o[2 * c + 1] = v.y + bv[2 * c + 1];
            }
            if (do_relu) {
                #pragma unroll
                for (int j = 0; j < 8; j++) o[j] = fmaxf(o[j], 0.0f);
            }
            float4* dst = (float4*)(out + (size_t)grow * 128 + tx * 8);
            dst[0] = make_float4(o[0], o[1], o[2], o[3]);
            dst[1] = make_float4(o[4], o[5], o[6], o[7]);
        }
    }
}

// ---------------- pooling (batch is sorted) ----------------
__global__ void pool_kernel(const float* __restrict__ h,
                            const int* __restrict__ batch) {
    int t = threadIdx.x;              // feature column, 128 threads
    int r0 = blockIdx.x * 128;
    if (r0 >= N_NODES) return;
    int r1 = r0 + 128; if (r1 > N_NODES) r1 = N_NODES;
    int gprev = batch[r0];
    float acc = 0.0f;
    float cacc = 0.0f;
    for (int r = r0; r < r1; r++) {
        int g = batch[r];
        if (g != gprev) {
            atomicAdd(&g_gsum[gprev * HID + t], acc);
            if (t == 0) atomicAdd(&g_gcnt[gprev], cacc);
            acc = 0.0f; cacc = 0.0f; gprev = g;
        }
        acc += h[(size_t)r * HID + t];
        cacc += 1.0f;
    }
    atomicAdd(&g_gsum[gprev * HID + t], acc);
    if (t == 0) atomicAdd(&g_gcnt[gprev], cacc);
}

// ---------------- final: out[g][o] = mean_pool @ fc^T + fc_b ----------------
__global__ void final_kernel(const float* __restrict__ fcW,
                             const float* __restrict__ fcb,
                             float* __restrict__ out) {
    int t = threadIdx.x;
    if (t >= N_GRAPHS * D_OUT) return;
    int g = t / D_OUT, o = t % D_OUT;
    float cnt = g_gcnt[g];
    float inv = 1.0f / fmaxf(cnt, 1.0f);
    float s = 0.0f;
    #pragma unroll 8
    for (int k = 0; k < HID; k++)
        s += g_gsum[g * HID + k] * fcW[o * HID + k];
    out[g * D_OUT + o] = s * inv + fcb[o];
}

// ---------------- launch ----------------
extern "C" void kernel_launch(void* const* d_in, const int* in_sizes, int n_in,
                              void* d_out, int out_size) {
    const float* x    = (const float*)d_in[0];
    const float* Wl0  = (const float*)d_in[1];
    const float* bl0  = (const float*)d_in[2];
    const float* Wr0  = (const float*)d_in[3];
    const float* W1   = (const float*)d_in[4];
    const float* b1   = (const float*)d_in[5];
    const float* Wl1  = (const float*)d_in[6];
    const float* bl1  = (const float*)d_in[7];
    const float* Wr1  = (const float*)d_in[8];
    const float* fcW  = (const float*)d_in[9];
    const float* fcb  = (const float*)d_in[10];
    const int*   ei   = (const int*)d_in[11];     // int64 in reference -> int32 in harness
    const int*   batch= (const int*)d_in[12];
    float*       out  = (float*)d_out;

    const int* src = ei;
    const int* dst = ei + N_EDGES;

    void *pAg = nullptr, *pA = nullptr, *pB = nullptr;
    cudaGetSymbolAddress(&pAg, g_aggr);
    cudaGetSymbolAddress(&pA,  g_bufA);
    cudaGetSymbolAddress(&pB,  g_bufB);
    float* aggr = (float*)pAg;
    float* bufA = (float*)pA;
    float* bufB = (float*)pB;

    const int SMEM = 2 * 16384 * sizeof(float);  // 131072
    cudaFuncSetAttribute(gemm_kernel, cudaFuncAttributeMaxDynamicSharedMemorySize, SMEM);

    int gemm_blocks = (N_NODES + 127) / 128;

    zero_kernel<<<(N_NODES + 255) / 256, 256>>>();
    hist_kernel<<<(N_EDGES + 255) / 256, 256>>>(dst);
    scan_kernel<<<1, 1024>>>();
    fill_kernel<<<(N_EDGES + 255) / 256, 256>>>(src, dst);

    // conv0: aggr(x) -> bufA = relu(aggr@Wl0^T + x@Wr0^T + bl0)
    agg_kernel<<<(N_NODES + 7) / 8, 256>>>(x, aggr);
    gemm_kernel<<<gemm_blocks, 256, SMEM>>>(aggr, Wl0, x, Wr0, bl0, bufA, N_NODES, 1, 1);

    // lin1: bufB = relu(bufA@W1^T + b1)
    gemm_kernel<<<gemm_blocks, 256, SMEM>>>(bufA, W1, nullptr, nullptr, b1, bufB, N_NODES, 1, 0);

    // conv1: aggr(bufB) -> bufA = relu(aggr@Wl1^T + bufB@Wr1^T + bl1)
    agg_kernel<<<(N_NODES + 7) / 8, 256>>>(bufB, aggr);
    gemm_kernel<<<gemm_blocks, 256, SMEM>>>(aggr, Wl1, bufB, Wr1, bl1, bufA, N_NODES, 1, 1);

    // pool + fc
    pool_kernel<<<(N_NODES + 127) / 128, 128>>>(bufA, batch);
    final_kernel<<<1, 96>>>(fcW, fcb, out);
}